// round 4
// baseline (speedup 1.0000x reference)
#include <cuda_runtime.h>
#include <cstdint>

// Problem constants (fixed shapes from reference)
#define B_ROWS 16384
#define T_LEN  4096
#define WORDS  (T_LEN / 32)    // 128 mask words per row
#define CHUNKS (T_LEN / 128)   // 32 warp-chunks (128 elems each) per row
#define THREADS 256
#define RPB    8               // rows per block

// Spread 8 bits (positions 0..7) to positions 0,4,8,...,28.
__device__ __forceinline__ uint32_t spread4(uint32_t x)
{
    x &= 0xffu;
    x = (x | (x << 12)) & 0x000F000Fu;
    x = (x | (x << 6))  & 0x03030303u;
    x = (x | (x << 3))  & 0x11111111u;
    return x;
}

__device__ __forceinline__ uint32_t smem_u32(const void* p)
{
    return (uint32_t)__cvta_generic_to_shared(p);
}

__device__ __forceinline__ void copy_row_async(const int* __restrict__ gsrc,
                                               const int4* sdst, int tid)
{
    const char* src = (const char*)gsrc;
    const uint32_t dst = smem_u32(sdst);
#pragma unroll
    for (int i = 0; i < 4; i++) {
        const int idx16 = i * 256 + tid;   // int4 index within the row
        asm volatile("cp.async.cg.shared.global [%0], [%1], 16;\n"
                     :: "r"(dst + idx16 * 16), "l"(src + (size_t)idx16 * 16));
    }
    asm volatile("cp.async.commit_group;\n");
}

__global__ void __launch_bounds__(THREADS)
yawning_adjust_kernel(const float* __restrict__ drowsiness,
                      const int* __restrict__ gesture,
                      float* __restrict__ out)
{
    __shared__ int4     buf[2][T_LEN / 4];   // 2 x 16 KB row stages
    __shared__ uint32_t sball[CHUNKS * 4];   // raw interleaved ballots
    __shared__ int      sred[THREADS / 32];

    const int tid  = threadIdx.x;
    const int lane = tid & 31;
    const int warp = tid >> 5;               // 0..7
    const int row0 = blockIdx.x * RPB;

    // Prologue: start copy of row 0 into stage 0.
    copy_row_async(gesture + (size_t)row0 * T_LEN, &buf[0][0], tid);

#pragma unroll 1
    for (int rr = 0; rr < RPB; rr++) {
        const int row = row0 + rr;
        const int cur = rr & 1, nxt = cur ^ 1;

        // Prefetch next row (clamped on last iteration; redundant but harmless).
        const int nrow = (rr + 1 < RPB) ? row + 1 : row;
        copy_row_async(gesture + (size_t)nrow * T_LEN, &buf[nxt][0], tid);

        // Wait for row r's copy (allow the just-committed prefetch to fly).
        asm volatile("cp.async.wait_group 1;\n" ::: "memory");
        __syncthreads();

        // ── Ballot packing from shared. Warp w covers chunks {w, 8+w, 16+w, 24+w}. ──
#pragma unroll
        for (int i = 0; i < 4; i++) {
            const int c = i * 8 + warp;
            const int4 g = buf[cur][c * 32 + lane];
            const uint32_t b0 = __ballot_sync(0xffffffffu, g.x == 2);
            const uint32_t b1 = __ballot_sync(0xffffffffu, g.y == 2);
            const uint32_t b2 = __ballot_sync(0xffffffffu, g.z == 2);
            const uint32_t b3 = __ballot_sync(0xffffffffu, g.w == 2);
            if (lane == 0) {
                sball[c * 4 + 0] = b0;
                sball[c * 4 + 1] = b1;
                sball[c * 4 + 2] = b2;
                sball[c * 4 + 3] = b3;
            }
        }
        __syncthreads();

        // ── Per-word streak counting. Each thread de-interleaves its own word
        //    AND the next word (no cross-thread smem dependency).
        //    Streak >= L exists iff a start (m[t] && !m[t-1]) has m[t..t+L-1] set.
        int packed = 0;   // hc | (lc << 16)
        if (tid < WORDS) {
            const int w = tid;
            uint32_t wcur = 0, wnxt = 0;
            {
                const int c = w >> 2, j = w & 3;
#pragma unroll
                for (int k = 0; k < 4; k++)
                    wcur |= spread4(sball[c * 4 + k] >> (8 * j)) << k;
            }
            if (w + 1 < WORDS) {
                const int c = (w + 1) >> 2, j = (w + 1) & 3;
#pragma unroll
                for (int k = 0; k < 4; k++)
                    wnxt |= spread4(sball[c * 4 + k] >> (8 * j)) << k;
            }
            uint32_t prevbit = 0;
            if (w > 0) {
                const int c = (w - 1) >> 2, j = (w - 1) & 3;
                // bit 31 of word w-1 = ballot 3, bit 8j+7
                prevbit = (sball[c * 4 + 3] >> (8 * j + 7)) & 1u;
            }

            const uint64_t ext = ((uint64_t)wnxt << 32) | (uint64_t)wcur;
            const uint32_t starts = wcur & ~((wcur << 1) | prevbit);
            const uint64_t r4 = ext & (ext >> 1) & (ext >> 2) & (ext >> 3);
            const uint64_t r7 = r4  & (ext >> 4) & (ext >> 5) & (ext >> 6);

            const int hc = __popc(starts & (uint32_t)r4);
            const int lc = __popc(starts & (uint32_t)r7);
            packed = hc | (lc << 16);
        }

        // ── Block reduction ──
#pragma unroll
        for (int off = 16; off > 0; off >>= 1)
            packed += __shfl_down_sync(0xffffffffu, packed, off);
        if (lane == 0) sred[warp] = packed;
        __syncthreads();   // publishes sred; also gates sball/buf reuse next iter

        if (tid == 0) {
            int tot = 0;
#pragma unroll
            for (int i = 0; i < THREADS / 32; i++) tot += sred[i];
            const int hc = tot & 0xffff;
            const int lc = tot >> 16;

            float hadj = (hc >= 2) ? 0.18f * expf(-0.5f * (float)(hc - 2)) : 0.0f;
            float ladj = (lc >= 3) ? 0.05f * expf(-0.5f * (float)(lc - 3)) : 0.0f;
            float adj = fminf(hadj + ladj, 0.35f);
            float r = drowsiness[row] + adj;
            out[row] = fminf(fmaxf(r, 0.0f), 1.0f);
        }
    }
}

extern "C" void kernel_launch(void* const* d_in, const int* in_sizes, int n_in,
                              void* d_out, int out_size)
{
    const float* drowsiness = (const float*)d_in[0];   // [B, 1] fp32
    const int*   gesture    = (const int*)d_in[1];     // [B, T, 1] int32
    float*       out        = (float*)d_out;           // [B, 1] fp32
    (void)in_sizes; (void)n_in; (void)out_size;

    yawning_adjust_kernel<<<B_ROWS / RPB, THREADS>>>(drowsiness, gesture, out);
}

// round 7
// speedup vs baseline: 1.0901x; 1.0901x over previous
#include <cuda_runtime.h>
#include <cstdint>

// Problem constants (fixed shapes from reference)
#define B_ROWS 16384
#define T_LEN  4096
#define WORDS  (T_LEN / 32)    // 128 mask words per row
#define CHUNKS (T_LEN / 128)   // 32 warp-chunks (128 elems each) per row
#define THREADS 256
#define RPB    2               // rows per block, processed concurrently

// Spread 8 bits (positions 0..7) to positions 0,4,8,...,28.
__device__ __forceinline__ uint32_t spread4(uint32_t x)
{
    x &= 0xffu;
    x = (x | (x << 12)) & 0x000F000Fu;
    x = (x | (x << 6))  & 0x03030303u;
    x = (x | (x << 3))  & 0x11111111u;
    return x;
}

__global__ void __launch_bounds__(THREADS)
yawning_adjust_kernel(const float* __restrict__ drowsiness,
                      const int* __restrict__ gesture,
                      float* __restrict__ out)
{
    __shared__ uint32_t sball[RPB][CHUNKS * 4];  // raw interleaved ballots
    __shared__ int      sred[THREADS / 32];

    const int tid  = threadIdx.x;
    const int lane = tid & 31;
    const int warp = tid >> 5;               // 0..7
    const int row0 = blockIdx.x * RPB;

    const int4* __restrict__ g4a = (const int4*)(gesture + (size_t)row0 * T_LEN);
    const int4* __restrict__ g4b = (const int4*)(gesture + (size_t)(row0 + 1) * T_LEN);

    // ── Phase 1: issue ALL 8 LDG.128 (32 KB) before any consumption ──────
    // Warp w covers chunks {w, 8+w, 16+w, 24+w} of each row; lane l loads
    // int4 at element c*128 + l*4 (fully coalesced, streaming).
    int4 ga[4], gb[4];
#pragma unroll
    for (int i = 0; i < 4; i++) {
        const int idx = (i * 8 + warp) * 32 + lane;
        ga[i] = __ldcs(&g4a[idx]);
        gb[i] = __ldcs(&g4b[idx]);
    }

    // ── Phase 2: ballot packing for both rows ────────────────────────────
#pragma unroll
    for (int i = 0; i < 4; i++) {
        const int c = i * 8 + warp;
        uint32_t b0 = __ballot_sync(0xffffffffu, ga[i].x == 2);
        uint32_t b1 = __ballot_sync(0xffffffffu, ga[i].y == 2);
        uint32_t b2 = __ballot_sync(0xffffffffu, ga[i].z == 2);
        uint32_t b3 = __ballot_sync(0xffffffffu, ga[i].w == 2);
        if (lane == 0) {
            sball[0][c * 4 + 0] = b0;
            sball[0][c * 4 + 1] = b1;
            sball[0][c * 4 + 2] = b2;
            sball[0][c * 4 + 3] = b3;
        }
        b0 = __ballot_sync(0xffffffffu, gb[i].x == 2);
        b1 = __ballot_sync(0xffffffffu, gb[i].y == 2);
        b2 = __ballot_sync(0xffffffffu, gb[i].z == 2);
        b3 = __ballot_sync(0xffffffffu, gb[i].w == 2);
        if (lane == 0) {
            sball[1][c * 4 + 0] = b0;
            sball[1][c * 4 + 1] = b1;
            sball[1][c * 4 + 2] = b2;
            sball[1][c * 4 + 3] = b3;
        }
    }
    __syncthreads();

    // ── Phase 3: per-word streak counting, all 256 threads active ────────
    // Thread t handles word w = t&127 of row rs = t>>7. Each thread
    // de-interleaves its own word AND the next word from the raw ballots
    // (no cross-thread smem dependency). A streak of length >= L exists iff
    // some start position (m[t] && !m[t-1]) has m[t..t+L-1] all set.
    const int rs = tid >> 7;         // row select, constant per warp
    const int w  = tid & (WORDS - 1);
    const uint32_t* __restrict__ bb = sball[rs];

    uint32_t wcur = 0, wnxt = 0;
    {
        const int c = w >> 2, j = w & 3;
#pragma unroll
        for (int k = 0; k < 4; k++)
            wcur |= spread4(bb[c * 4 + k] >> (8 * j)) << k;
    }
    if (w + 1 < WORDS) {
        const int c = (w + 1) >> 2, j = (w + 1) & 3;
#pragma unroll
        for (int k = 0; k < 4; k++)
            wnxt |= spread4(bb[c * 4 + k] >> (8 * j)) << k;
    }
    uint32_t prevbit = 0;
    if (w > 0) {
        const int c = (w - 1) >> 2, j = (w - 1) & 3;
        // bit 31 of word w-1 = ballot 3, bit 8j+7
        prevbit = (bb[c * 4 + 3] >> (8 * j + 7)) & 1u;
    }

    const uint64_t ext = ((uint64_t)wnxt << 32) | (uint64_t)wcur;
    const uint32_t starts = wcur & ~((wcur << 1) | prevbit);
    const uint64_t r4 = ext & (ext >> 1) & (ext >> 2) & (ext >> 3);
    const uint64_t r7 = r4  & (ext >> 4) & (ext >> 5) & (ext >> 6);

    int packed = __popc(starts & (uint32_t)r4)
               | (__popc(starts & (uint32_t)r7) << 16);   // hc | (lc<<16)

    // ── Phase 4: reduction (warps 0-3 -> row 0, warps 4-7 -> row 1) ──────
#pragma unroll
    for (int off = 16; off > 0; off >>= 1)
        packed += __shfl_down_sync(0xffffffffu, packed, off);
    if (lane == 0) sred[warp] = packed;
    __syncthreads();

    if ((tid & 127) == 0) {                   // tid 0 -> row0, tid 128 -> row1
        const int base = rs * 4;
        int tot = sred[base] + sred[base + 1] + sred[base + 2] + sred[base + 3];
        const int hc = tot & 0xffff;
        const int lc = tot >> 16;

        float hadj = (hc >= 2) ? 0.18f * expf(-0.5f * (float)(hc - 2)) : 0.0f;
        float ladj = (lc >= 3) ? 0.05f * expf(-0.5f * (float)(lc - 3)) : 0.0f;
        float adj = fminf(hadj + ladj, 0.35f);
        float r = drowsiness[row0 + rs] + adj;
        out[row0 + rs] = fminf(fmaxf(r, 0.0f), 1.0f);
    }
}

extern "C" void kernel_launch(void* const* d_in, const int* in_sizes, int n_in,
                              void* d_out, int out_size)
{
    const float* drowsiness = (const float*)d_in[0];   // [B, 1] fp32
    const int*   gesture    = (const int*)d_in[1];     // [B, T, 1] int32
    float*       out        = (float*)d_out;           // [B, 1] fp32
    (void)in_sizes; (void)n_in; (void)out_size;

    yawning_adjust_kernel<<<B_ROWS / RPB, THREADS>>>(drowsiness, gesture, out);
}

// round 8
// speedup vs baseline: 1.0972x; 1.0066x over previous
#include <cuda_runtime.h>
#include <cstdint>

// Problem constants (fixed shapes from reference)
#define B_ROWS 16384
#define T_LEN  4096
#define WORDS  (T_LEN / 32)    // 128 mask words per row
#define CHUNKS (T_LEN / 128)   // 32 warp-chunks (128 elems each) per row
#define THREADS 256
#define GRID   2048
#define ITERS  (B_ROWS / GRID) // 8 rows per block, register double-buffered

// Spread 8 bits (positions 0..7) to positions 0,4,8,...,28.
__device__ __forceinline__ uint32_t spread4(uint32_t x)
{
    x &= 0xffu;
    x = (x | (x << 12)) & 0x000F000Fu;
    x = (x | (x << 6))  & 0x03030303u;
    x = (x | (x << 3))  & 0x11111111u;
    return x;
}

__global__ void __launch_bounds__(THREADS)
yawning_adjust_kernel(const float* __restrict__ drowsiness,
                      const int* __restrict__ gesture,
                      float* __restrict__ out)
{
    __shared__ uint32_t sball[CHUNKS * 4];   // raw interleaved ballots
    __shared__ int      sred[THREADS / 32];

    const int tid  = threadIdx.x;
    const int lane = tid & 31;
    const int warp = tid >> 5;               // 0..7

    // Each warp covers chunks {warp, 8+warp, 16+warp, 24+warp} of each row;
    // lane l loads int4 at element c*128 + l*4 (LDG.128, fully coalesced).
    int idx4[4];
#pragma unroll
    for (int i = 0; i < 4; i++)
        idx4[i] = (i * 8 + warp) * 32 + lane;

    int row = blockIdx.x;

    // Prologue: prefetch row 0 of this block's stripe.
    int4 p[4];
    {
        const int4* __restrict__ g4 = (const int4*)(gesture + (size_t)row * T_LEN);
#pragma unroll
        for (int i = 0; i < 4; i++) p[i] = __ldcs(&g4[idx4[i]]);
    }

#pragma unroll 1
    for (int it = 0; it < ITERS; it++) {
        // Working copy of the prefetched row; immediately issue next row's
        // loads so the memory stream stays live through the compute tail.
        int4 g[4];
#pragma unroll
        for (int i = 0; i < 4; i++) g[i] = p[i];

        if (it + 1 < ITERS) {
            const int4* __restrict__ g4n =
                (const int4*)(gesture + (size_t)(row + GRID) * T_LEN);
#pragma unroll
            for (int i = 0; i < 4; i++) p[i] = __ldcs(&g4n[idx4[i]]);
        }

        // ── Ballot packing ───────────────────────────────────────────────
#pragma unroll
        for (int i = 0; i < 4; i++) {
            const int c = i * 8 + warp;
            const uint32_t b0 = __ballot_sync(0xffffffffu, g[i].x == 2);
            const uint32_t b1 = __ballot_sync(0xffffffffu, g[i].y == 2);
            const uint32_t b2 = __ballot_sync(0xffffffffu, g[i].z == 2);
            const uint32_t b3 = __ballot_sync(0xffffffffu, g[i].w == 2);
            if (lane == 0) {
                sball[c * 4 + 0] = b0;
                sball[c * 4 + 1] = b1;
                sball[c * 4 + 2] = b2;
                sball[c * 4 + 3] = b3;
            }
        }
        __syncthreads();

        // ── Per-word streak counting (threads 0..127) ────────────────────
        // Each thread de-interleaves its own mask word AND the next word
        // from the raw ballots (no cross-thread smem dependency). A streak
        // of length >= L exists iff some start (m[t] && !m[t-1]) has
        // m[t..t+L-1] all set; window is <=6 bits ahead, 1 bit behind.
        int packed = 0;   // hc | (lc << 16)
        if (tid < WORDS) {
            const int w = tid;
            uint32_t wcur = 0, wnxt = 0;
            {
                const int c = w >> 2, j = w & 3;
#pragma unroll
                for (int k = 0; k < 4; k++)
                    wcur |= spread4(sball[c * 4 + k] >> (8 * j)) << k;
            }
            if (w + 1 < WORDS) {
                const int c = (w + 1) >> 2, j = (w + 1) & 3;
#pragma unroll
                for (int k = 0; k < 4; k++)
                    wnxt |= spread4(sball[c * 4 + k] >> (8 * j)) << k;
            }
            uint32_t prevbit = 0;
            if (w > 0) {
                const int c = (w - 1) >> 2, j = (w - 1) & 3;
                // bit 31 of word w-1 = ballot 3, bit 8j+7
                prevbit = (sball[c * 4 + 3] >> (8 * j + 7)) & 1u;
            }

            const uint64_t ext = ((uint64_t)wnxt << 32) | (uint64_t)wcur;
            const uint32_t starts = wcur & ~((wcur << 1) | prevbit);
            const uint64_t r4 = ext & (ext >> 1) & (ext >> 2) & (ext >> 3);
            const uint64_t r7 = r4  & (ext >> 4) & (ext >> 5) & (ext >> 6);

            packed = __popc(starts & (uint32_t)r4)
                   | (__popc(starts & (uint32_t)r7) << 16);
        }

        // ── Block reduction + epilogue ───────────────────────────────────
#pragma unroll
        for (int off = 16; off > 0; off >>= 1)
            packed += __shfl_down_sync(0xffffffffu, packed, off);
        if (lane == 0) sred[warp] = packed;
        __syncthreads();   // publishes sred; also gates sball reuse next iter

        if (tid == 0) {
            int tot = 0;
#pragma unroll
            for (int i = 0; i < THREADS / 32; i++) tot += sred[i];
            const int hc = tot & 0xffff;
            const int lc = tot >> 16;

            float hadj = (hc >= 2) ? 0.18f * expf(-0.5f * (float)(hc - 2)) : 0.0f;
            float ladj = (lc >= 3) ? 0.05f * expf(-0.5f * (float)(lc - 3)) : 0.0f;
            float adj = fminf(hadj + ladj, 0.35f);
            float r = drowsiness[row] + adj;
            out[row] = fminf(fmaxf(r, 0.0f), 1.0f);
        }

        row += GRID;
    }
}

extern "C" void kernel_launch(void* const* d_in, const int* in_sizes, int n_in,
                              void* d_out, int out_size)
{
    const float* drowsiness = (const float*)d_in[0];   // [B, 1] fp32
    const int*   gesture    = (const int*)d_in[1];     // [B, T, 1] int32
    float*       out        = (float*)d_out;           // [B, 1] fp32
    (void)in_sizes; (void)n_in; (void)out_size;

    yawning_adjust_kernel<<<GRID, THREADS>>>(drowsiness, gesture, out);
}